// round 2
// baseline (speedup 1.0000x reference)
#include <cuda_runtime.h>
#include <cuda_bf16.h>
#include <cstdint>

// Problem sizes (fixed by the dataset)
#define MB   16
#define TT   512
#define NDIM 2048
#define UU   64
#define MTOT (MB*TT)   // 8192

// ----------------------------------------------------------------------------
// Scratch (__device__ globals — allocation-free per harness rules)
// A = rna_tf32(x)            [MTOT, NDIM]  fp32-bits (tf32-rounded)
// B = rna_tf32(Adj * wbar)   [NDIM, NDIM]
// ----------------------------------------------------------------------------
__device__ __align__(16) float g_wbar[NDIM];
__device__ float g_bmean;
__device__ __align__(16) float g_A[(size_t)MTOT * NDIM];
__device__ __align__(16) float g_B[(size_t)NDIM * NDIM];

// ----------------------------------------------------------------------------
// Helpers
// ----------------------------------------------------------------------------
__device__ __forceinline__ uint32_t smem_to_u32(const void* p) {
    uint32_t a;
    asm("{ .reg .u64 t; cvta.to.shared.u64 t, %1; cvt.u32.u64 %0, t; }" : "=r"(a) : "l"(p));
    return a;
}

__device__ __forceinline__ uint32_t f2tf32(float f) {
    uint32_t u;
    asm("cvt.rna.tf32.f32 %0, %1;" : "=r"(u) : "f"(f));
    return u;
}

__device__ __forceinline__ void cp16(uint32_t s, const void* g) {
    asm volatile("cp.async.cg.shared.global [%0], [%1], 16;" :: "r"(s), "l"(g));
}
__device__ __forceinline__ void cp_commit() { asm volatile("cp.async.commit_group;" ::: "memory"); }
template<int N> __device__ __forceinline__ void cp_wait() {
    asm volatile("cp.async.wait_group %0;" :: "n"(N) : "memory");
}

__device__ __forceinline__ void ldm_x4(uint32_t* r, uint32_t addr) {
    asm volatile("ldmatrix.sync.aligned.m8n8.x4.shared.b16 {%0,%1,%2,%3}, [%4];"
                 : "=r"(r[0]), "=r"(r[1]), "=r"(r[2]), "=r"(r[3]) : "r"(addr));
}

__device__ __forceinline__ void mma_tf32(float* c, const uint32_t* a, const uint32_t* b) {
    asm volatile(
        "mma.sync.aligned.m16n8k8.row.col.f32.tf32.tf32.f32 "
        "{%0,%1,%2,%3}, {%4,%5,%6,%7}, {%8,%9}, {%0,%1,%2,%3};"
        : "+f"(c[0]), "+f"(c[1]), "+f"(c[2]), "+f"(c[3])
        : "r"(a[0]), "r"(a[1]), "r"(a[2]), "r"(a[3]), "r"(b[0]), "r"(b[1]));
}

// ----------------------------------------------------------------------------
// Prep kernels
// ----------------------------------------------------------------------------
__global__ void prep_wbar_kernel(const float* __restrict__ W, const float* __restrict__ bias) {
    int k = blockIdx.x * blockDim.x + threadIdx.x;
    if (k < NDIM) {
        float s = 0.f;
        #pragma unroll 8
        for (int i = 0; i < UU; i++) s += W[i * NDIM + k];
        g_wbar[k] = s * (1.0f / UU);
    }
    if (blockIdx.x == 0 && threadIdx.x == 0) {
        float s = 0.f;
        for (int i = 0; i < UU; i++) s += bias[i];
        g_bmean = s * (1.0f / UU);
    }
}

// B[j,k] = tf32(Adj[j,k] * wbar[k])
__global__ void conv_B_kernel(const float* __restrict__ Adj) {
    size_t base = ((size_t)blockIdx.x * blockDim.x + threadIdx.x) * 4;
    float4 a = *reinterpret_cast<const float4*>(Adj + base);
    int k0 = (int)(base & (NDIM - 1));
    float4 wb = *reinterpret_cast<const float4*>(g_wbar + k0);
    uint4 o;
    o.x = f2tf32(a.x * wb.x);
    o.y = f2tf32(a.y * wb.y);
    o.z = f2tf32(a.z * wb.z);
    o.w = f2tf32(a.w * wb.w);
    *reinterpret_cast<uint4*>(reinterpret_cast<uint32_t*>(g_B) + base) = o;
}

// A[m,k] = tf32(x[m,k])
__global__ void conv_A_kernel(const float* __restrict__ x) {
    size_t base = ((size_t)blockIdx.x * blockDim.x + threadIdx.x) * 4;
    float4 a = *reinterpret_cast<const float4*>(x + base);
    uint4 o;
    o.x = f2tf32(a.x);
    o.y = f2tf32(a.y);
    o.z = f2tf32(a.z);
    o.w = f2tf32(a.w);
    *reinterpret_cast<uint4*>(reinterpret_cast<uint32_t*>(g_A) + base) = o;
}

// ----------------------------------------------------------------------------
// GEMM: out[m, j] = sum_k A[m,k] * B[j,k] + bmean
// CTA tile 128x128, warp tile 64x32 (2x4 warps), KC=32 fp32 (128B rows),
// 4-stage cp.async pipeline, mma.sync.m16n8k8 tf32.
// ----------------------------------------------------------------------------
static constexpr int TM = 128;
static constexpr int TN = 128;
static constexpr int KC = 32;                  // floats per k-chunk
static constexpr int NKC = NDIM / KC;          // 64
static constexpr int STAGES = 4;

static constexpr int A_STAGE = TM * 128;       // 16384 B (128B per row)
static constexpr int B_STAGE = TN * 128;       // 16384 B
static constexpr int STAGE_BYTES = A_STAGE + B_STAGE;      // 32768
static constexpr int SMEM_TOTAL = STAGES * STAGE_BYTES;    // 131072

// swizzled offset within a tile: row (0..127) x 16B-chunk c (0..7)
__device__ __forceinline__ uint32_t swz(int row, int c) {
    return (uint32_t)(row * 128 + ((c ^ (row & 7)) << 4));
}

__global__ __launch_bounds__(256, 1) void gemm_kernel(float* __restrict__ out) {
    extern __shared__ char smem[];
    uint32_t sb = smem_to_u32(smem);

    const int tid = threadIdx.x;
    const int wid = tid >> 5, lid = tid & 31;
    const int wm = wid >> 2;          // 0..1  (64 rows each)
    const int wn = wid & 3;           // 0..3  (32 cols each)
    const int m0 = blockIdx.y * TM;
    const int n0 = blockIdx.x * TN;

    // global load pointers for this CTA (bytes)
    const char* gA = reinterpret_cast<const char*>(g_A + (size_t)m0 * NDIM);
    const char* gB = reinterpret_cast<const char*>(g_B + (size_t)n0 * NDIM);

    // cp.async granule assignment: 2048 granules (1024 A + 1024 B), 8 per thread
    // granule gi: first 1024 -> A row=gi>>3 chunk=gi&7 ; else B
    auto load_stage = [&](int kc, int stage) {
        uint32_t abase = sb + stage * STAGE_BYTES;
        uint32_t bbase = abase + A_STAGE;
        size_t koff = (size_t)kc * KC * 4;   // byte offset along k
        #pragma unroll
        for (int j = 0; j < 8; j++) {
            int gi = tid + j * 256;
            int r = (gi >> 3) & 127, c = gi & 7;
            if (gi < 1024) {
                cp16(abase + swz(r, c), gA + (size_t)r * (NDIM * 4) + koff + c * 16);
            } else {
                cp16(bbase + swz(r, c), gB + (size_t)r * (NDIM * 4) + koff + c * 16);
            }
        }
    };

    // ldmatrix per-thread row/chunk roles
    // A (per mb block of 16 rows): t0-15 -> row base+t, chunk +0 ; t16-31 -> row base+(t-16), chunk +1
    const int aRowOff = (lid & 15);
    const int aCsel = lid >> 4;
    // B (per pair of n8 blocks): rows 0..15 within pair: (lid&7) + ((lid>>4)<<3) ; chunk +((lid>>3)&1)
    const int bRowOff = (lid & 7) + ((lid >> 4) << 3);
    const int bCsel = (lid >> 3) & 1;

    float acc[4][4][4];
    #pragma unroll
    for (int i = 0; i < 4; i++)
        #pragma unroll
        for (int j = 0; j < 4; j++)
            #pragma unroll
            for (int q = 0; q < 4; q++) acc[i][j][q] = 0.f;

    // Prologue: prefetch 3 stages
    #pragma unroll
    for (int s = 0; s < 3; s++) { load_stage(s, s); cp_commit(); }

    for (int i = 0; i < NKC; i++) {
        if (i + 3 < NKC) load_stage(i + 3, (i + 3) & (STAGES - 1));
        cp_commit();                   // empty group when nothing issued
        cp_wait<3>();
        __syncthreads();

        uint32_t abase = sb + (i & (STAGES - 1)) * STAGE_BYTES;
        uint32_t bbase = abase + A_STAGE;

        #pragma unroll
        for (int ks = 0; ks < KC / 8; ks++) {
            uint32_t aR[4][4], bR[2][4];
            #pragma unroll
            for (int mb = 0; mb < 4; mb++) {
                int row = wm * 64 + mb * 16 + aRowOff;
                ldm_x4(aR[mb], abase + swz(row, ks * 2 + aCsel));
            }
            #pragma unroll
            for (int bp = 0; bp < 2; bp++) {
                int row = wn * 32 + bp * 16 + bRowOff;
                ldm_x4(bR[bp], bbase + swz(row, ks * 2 + bCsel));
            }
            #pragma unroll
            for (int mb = 0; mb < 4; mb++) {
                #pragma unroll
                for (int nb = 0; nb < 4; nb++) {
                    mma_tf32(acc[mb][nb], aR[mb], &bR[nb >> 1][(nb & 1) * 2]);
                }
            }
        }
        __syncthreads();
    }

    // Epilogue
    float bm = g_bmean;
    #pragma unroll
    for (int mb = 0; mb < 4; mb++) {
        int row = m0 + wm * 64 + mb * 16 + (lid >> 2);
        #pragma unroll
        for (int nb = 0; nb < 4; nb++) {
            int col = n0 + wn * 32 + nb * 8 + (lid & 3) * 2;
            float2 v0, v1;
            v0.x = acc[mb][nb][0] + bm;
            v0.y = acc[mb][nb][1] + bm;
            v1.x = acc[mb][nb][2] + bm;
            v1.y = acc[mb][nb][3] + bm;
            *reinterpret_cast<float2*>(out + (size_t)row * NDIM + col) = v0;
            *reinterpret_cast<float2*>(out + (size_t)(row + 8) * NDIM + col) = v1;
        }
    }
}

// ----------------------------------------------------------------------------
// Launch
// ----------------------------------------------------------------------------
extern "C" void kernel_launch(void* const* d_in, const int* in_sizes, int n_in,
                              void* d_out, int out_size) {
    const float* x    = (const float*)d_in[0];   // [16, 512, 2048]
    const float* Adj  = (const float*)d_in[1];   // [2048, 2048]
    const float* W    = (const float*)d_in[2];   // [64, 2048]
    const float* bias = (const float*)d_in[3];   // [64]
    float* out = (float*)d_out;                  // [16, 512, 2048]

    prep_wbar_kernel<<<8, 256>>>(W, bias);
    conv_B_kernel<<<(NDIM * NDIM / 4) / 256, 256>>>(Adj);
    conv_A_kernel<<<(int)(((size_t)MTOT * NDIM / 4) / 256), 256>>>(x);

    cudaFuncSetAttribute(gemm_kernel, cudaFuncAttributeMaxDynamicSharedMemorySize, SMEM_TOTAL);
    gemm_kernel<<<dim3(NDIM / TN, MTOT / TM), 256, SMEM_TOTAL>>>(out);
}

// round 3
// speedup vs baseline: 1.0573x; 1.0573x over previous
#include <cuda_runtime.h>
#include <cuda_bf16.h>
#include <cstdint>

// Problem sizes (fixed by the dataset)
#define MB   16
#define TT   512
#define NDIM 2048
#define UU   64
#define MTOT (MB*TT)   // 8192

// ----------------------------------------------------------------------------
// Scratch (__device__ globals — allocation-free per harness rules)
// B = rna_tf32(Adj * wbar)   [NDIM, NDIM]  (A is read directly from x, fused cvt)
// ----------------------------------------------------------------------------
__device__ __align__(16) float g_wbar[NDIM];
__device__ float g_bmean;
__device__ __align__(16) float g_B[(size_t)NDIM * NDIM];

// ----------------------------------------------------------------------------
// Helpers
// ----------------------------------------------------------------------------
__device__ __forceinline__ uint32_t smem_to_u32(const void* p) {
    uint32_t a;
    asm("{ .reg .u64 t; cvta.to.shared.u64 t, %1; cvt.u32.u64 %0, t; }" : "=r"(a) : "l"(p));
    return a;
}

__device__ __forceinline__ uint32_t f2tf32(float f) {
    uint32_t u;
    asm("cvt.rna.tf32.f32 %0, %1;" : "=r"(u) : "f"(f));
    return u;
}

__device__ __forceinline__ void cp16(uint32_t s, const void* g) {
    asm volatile("cp.async.cg.shared.global [%0], [%1], 16;" :: "r"(s), "l"(g));
}
__device__ __forceinline__ void cp_commit() { asm volatile("cp.async.commit_group;" ::: "memory"); }
template<int N> __device__ __forceinline__ void cp_wait() {
    asm volatile("cp.async.wait_group %0;" :: "n"(N) : "memory");
}

__device__ __forceinline__ void ldm_x4(uint32_t* r, uint32_t addr) {
    asm volatile("ldmatrix.sync.aligned.m8n8.x4.shared.b16 {%0,%1,%2,%3}, [%4];"
                 : "=r"(r[0]), "=r"(r[1]), "=r"(r[2]), "=r"(r[3]) : "r"(addr));
}

__device__ __forceinline__ void mma_tf32(float* c, const uint32_t* a, const uint32_t* b) {
    asm volatile(
        "mma.sync.aligned.m16n8k8.row.col.f32.tf32.tf32.f32 "
        "{%0,%1,%2,%3}, {%4,%5,%6,%7}, {%8,%9}, {%0,%1,%2,%3};"
        : "+f"(c[0]), "+f"(c[1]), "+f"(c[2]), "+f"(c[3])
        : "r"(a[0]), "r"(a[1]), "r"(a[2]), "r"(a[3]), "r"(b[0]), "r"(b[1]));
}

// ----------------------------------------------------------------------------
// Prep kernels
// ----------------------------------------------------------------------------
__global__ void prep_wbar_kernel(const float* __restrict__ W, const float* __restrict__ bias) {
    int k = blockIdx.x * blockDim.x + threadIdx.x;
    if (k < NDIM) {
        float s = 0.f;
        #pragma unroll 8
        for (int i = 0; i < UU; i++) s += W[i * NDIM + k];
        g_wbar[k] = s * (1.0f / UU);
    }
    if (blockIdx.x == 0 && threadIdx.x == 0) {
        float s = 0.f;
        for (int i = 0; i < UU; i++) s += bias[i];
        g_bmean = s * (1.0f / UU);
    }
}

// B[j,k] = tf32(Adj[j,k] * wbar[k])
__global__ void conv_B_kernel(const float* __restrict__ Adj) {
    size_t base = ((size_t)blockIdx.x * blockDim.x + threadIdx.x) * 4;
    float4 a = *reinterpret_cast<const float4*>(Adj + base);
    int k0 = (int)(base & (NDIM - 1));
    float4 wb = *reinterpret_cast<const float4*>(g_wbar + k0);
    uint4 o;
    o.x = f2tf32(a.x * wb.x);
    o.y = f2tf32(a.y * wb.y);
    o.z = f2tf32(a.z * wb.z);
    o.w = f2tf32(a.w * wb.w);
    *reinterpret_cast<uint4*>(reinterpret_cast<uint32_t*>(g_B) + base) = o;
}

// ----------------------------------------------------------------------------
// GEMM: out[m, j] = sum_k tf32(x[m,k]) * B[j,k] + bmean
// CTA tile 128x128, warp tile 64x32 (2x4 warps), KC=32 fp32 (128B rows),
// 3-stage cp.async pipeline, single __syncthreads per chunk, 2 CTAs/SM.
// A is raw fp32 from x; cvt.rna.tf32 applied in registers post-ldmatrix.
// ----------------------------------------------------------------------------
static constexpr int TM = 128;
static constexpr int TN = 128;
static constexpr int KC = 32;                  // floats per k-chunk
static constexpr int NKC = NDIM / KC;          // 64
static constexpr int STAGES = 3;

static constexpr int A_STAGE = TM * 128;       // 16384 B (128B per row)
static constexpr int B_STAGE = TN * 128;       // 16384 B
static constexpr int STAGE_BYTES = A_STAGE + B_STAGE;      // 32768
static constexpr int SMEM_TOTAL = STAGES * STAGE_BYTES;    // 98304

// swizzled offset within a tile: row (0..127) x 16B-chunk c (0..7)
__device__ __forceinline__ uint32_t swz(int row, int c) {
    return (uint32_t)(row * 128 + ((c ^ (row & 7)) << 4));
}

__global__ __launch_bounds__(256, 2) void gemm_kernel(const float* __restrict__ x,
                                                      float* __restrict__ out) {
    extern __shared__ char smem[];
    uint32_t sb = smem_to_u32(smem);

    const int tid = threadIdx.x;
    const int wid = tid >> 5, lid = tid & 31;
    const int wm = wid >> 2;          // 0..1  (64 rows each)
    const int wn = wid & 3;           // 0..3  (32 cols each)
    const int m0 = blockIdx.y * TM;
    const int n0 = blockIdx.x * TN;

    // global load pointers for this CTA (bytes)
    const char* gA = reinterpret_cast<const char*>(x   + (size_t)m0 * NDIM);
    const char* gB = reinterpret_cast<const char*>(g_B + (size_t)n0 * NDIM);

    // per-thread fixed granule roles: 8 granules each (1024 A + 1024 B total)
    auto load_stage = [&](int kc, int stage) {
        uint32_t abase = sb + stage * STAGE_BYTES;
        uint32_t bbase = abase + A_STAGE;
        size_t koff = (size_t)kc * KC * 4;   // byte offset along k
        #pragma unroll
        for (int j = 0; j < 8; j++) {
            int gi = tid + j * 256;
            int r = (gi >> 3) & 127, c = gi & 7;
            if (gi < 1024) {
                cp16(abase + swz(r, c), gA + (size_t)r * (NDIM * 4) + koff + c * 16);
            } else {
                cp16(bbase + swz(r, c), gB + (size_t)r * (NDIM * 4) + koff + c * 16);
            }
        }
    };

    // ldmatrix per-thread row/chunk roles
    const int aRowOff = (lid & 15);
    const int aCsel = lid >> 4;
    const int bRowOff = (lid & 7) + ((lid >> 4) << 3);
    const int bCsel = (lid >> 3) & 1;

    float acc[4][4][4];
    #pragma unroll
    for (int i = 0; i < 4; i++)
        #pragma unroll
        for (int j = 0; j < 4; j++)
            #pragma unroll
            for (int q = 0; q < 4; q++) acc[i][j][q] = 0.f;

    // Prologue: prefetch STAGES-1 = 2 stages
    #pragma unroll
    for (int s = 0; s < STAGES - 1; s++) { load_stage(s, s); cp_commit(); }

    int stage = 0;
    for (int i = 0; i < NKC; i++) {
        cp_wait<STAGES - 2>();
        __syncthreads();

        uint32_t abase = sb + stage * STAGE_BYTES;
        uint32_t bbase = abase + A_STAGE;

        #pragma unroll
        for (int ks = 0; ks < KC / 8; ks++) {
            uint32_t aR[4][4], bR[2][4];
            #pragma unroll
            for (int mb = 0; mb < 4; mb++) {
                int row = wm * 64 + mb * 16 + aRowOff;
                ldm_x4(aR[mb], abase + swz(row, ks * 2 + aCsel));
                // fused tf32 rounding of raw fp32 x fragments
                #pragma unroll
                for (int q = 0; q < 4; q++)
                    aR[mb][q] = f2tf32(__uint_as_float(aR[mb][q]));
            }
            #pragma unroll
            for (int bp = 0; bp < 2; bp++) {
                int row = wn * 32 + bp * 16 + bRowOff;
                ldm_x4(bR[bp], bbase + swz(row, ks * 2 + bCsel));
            }

            // after first ks block's loads, kick off the next stage's cp.async
            if (ks == 0) {
                int nxt = i + STAGES - 1;
                if (nxt < NKC) {
                    int nstage = stage + (STAGES - 1);
                    if (nstage >= STAGES) nstage -= STAGES;
                    load_stage(nxt, nstage);
                }
                cp_commit();   // empty group near the tail keeps counts consistent
            }

            #pragma unroll
            for (int mb = 0; mb < 4; mb++) {
                #pragma unroll
                for (int nb = 0; nb < 4; nb++) {
                    mma_tf32(acc[mb][nb], aR[mb], &bR[nb >> 1][(nb & 1) * 2]);
                }
            }
        }

        stage++;
        if (stage == STAGES) stage = 0;
    }

    // Epilogue
    float bm = g_bmean;
    #pragma unroll
    for (int mb = 0; mb < 4; mb++) {
        int row = m0 + wm * 64 + mb * 16 + (lid >> 2);
        #pragma unroll
        for (int nb = 0; nb < 4; nb++) {
            int col = n0 + wn * 32 + nb * 8 + (lid & 3) * 2;
            float2 v0, v1;
            v0.x = acc[mb][nb][0] + bm;
            v0.y = acc[mb][nb][1] + bm;
            v1.x = acc[mb][nb][2] + bm;
            v1.y = acc[mb][nb][3] + bm;
            *reinterpret_cast<float2*>(out + (size_t)row * NDIM + col) = v0;
            *reinterpret_cast<float2*>(out + (size_t)(row + 8) * NDIM + col) = v1;
        }
    }
}

// ----------------------------------------------------------------------------
// Launch
// ----------------------------------------------------------------------------
extern "C" void kernel_launch(void* const* d_in, const int* in_sizes, int n_in,
                              void* d_out, int out_size) {
    const float* x    = (const float*)d_in[0];   // [16, 512, 2048]
    const float* Adj  = (const float*)d_in[1];   // [2048, 2048]
    const float* W    = (const float*)d_in[2];   // [64, 2048]
    const float* bias = (const float*)d_in[3];   // [64]
    float* out = (float*)d_out;                  // [16, 512, 2048]

    prep_wbar_kernel<<<8, 256>>>(W, bias);
    conv_B_kernel<<<(NDIM * NDIM / 4) / 256, 256>>>(Adj);

    cudaFuncSetAttribute(gemm_kernel, cudaFuncAttributeMaxDynamicSharedMemorySize, SMEM_TOTAL);
    gemm_kernel<<<dim3(NDIM / TN, MTOT / TM), 256, SMEM_TOTAL>>>(x, out);
}

// round 4
// speedup vs baseline: 1.2278x; 1.1613x over previous
#include <cuda_runtime.h>
#include <cuda_bf16.h>
#include <cstdint>

// Problem sizes (fixed by the dataset)
#define MB   16
#define TT   512
#define NDIM 2048
#define UU   64
#define MTOT (MB*TT)   // 8192

// ----------------------------------------------------------------------------
// Scratch (__device__ globals — allocation-free per harness rules)
// B = rna_tf32(Adj * wbar)   [NDIM, NDIM]  (A is read directly from x, fused cvt)
// ----------------------------------------------------------------------------
__device__ __align__(16) float g_wbar[NDIM];
__device__ float g_bmean;
__device__ __align__(16) float g_B[(size_t)NDIM * NDIM];

// ----------------------------------------------------------------------------
// Helpers
// ----------------------------------------------------------------------------
__device__ __forceinline__ uint32_t smem_to_u32(const void* p) {
    uint32_t a;
    asm("{ .reg .u64 t; cvta.to.shared.u64 t, %1; cvt.u32.u64 %0, t; }" : "=r"(a) : "l"(p));
    return a;
}

__device__ __forceinline__ uint32_t f2tf32(float f) {
    uint32_t u;
    asm("cvt.rna.tf32.f32 %0, %1;" : "=r"(u) : "f"(f));
    return u;
}

__device__ __forceinline__ void cp16(uint32_t s, const void* g) {
    asm volatile("cp.async.cg.shared.global [%0], [%1], 16;" :: "r"(s), "l"(g));
}
__device__ __forceinline__ void cp_commit() { asm volatile("cp.async.commit_group;" ::: "memory"); }
template<int N> __device__ __forceinline__ void cp_wait() {
    asm volatile("cp.async.wait_group %0;" :: "n"(N) : "memory");
}

__device__ __forceinline__ void ldm_x4(uint32_t* r, uint32_t addr) {
    asm volatile("ldmatrix.sync.aligned.m8n8.x4.shared.b16 {%0,%1,%2,%3}, [%4];"
                 : "=r"(r[0]), "=r"(r[1]), "=r"(r[2]), "=r"(r[3]) : "r"(addr));
}

__device__ __forceinline__ void mma_tf32(float* c, const uint32_t* a, const uint32_t* b) {
    asm volatile(
        "mma.sync.aligned.m16n8k8.row.col.f32.tf32.tf32.f32 "
        "{%0,%1,%2,%3}, {%4,%5,%6,%7}, {%8,%9}, {%0,%1,%2,%3};"
        : "+f"(c[0]), "+f"(c[1]), "+f"(c[2]), "+f"(c[3])
        : "r"(a[0]), "r"(a[1]), "r"(a[2]), "r"(a[3]), "r"(b[0]), "r"(b[1]));
}

// ----------------------------------------------------------------------------
// Prep kernels
// ----------------------------------------------------------------------------
// 16 blocks x 256 threads: each block covers 128 columns; tid>>7 selects row-half.
__global__ void prep_wbar_kernel(const float* __restrict__ W, const float* __restrict__ bias) {
    __shared__ float part[128];
    int col = blockIdx.x * 128 + (threadIdx.x & 127);
    int half = threadIdx.x >> 7;
    float s = 0.f;
    #pragma unroll 8
    for (int i = 0; i < UU / 2; i++) s += W[(half * (UU / 2) + i) * NDIM + col];
    if (half == 0) part[threadIdx.x] = s;
    __syncthreads();
    if (half == 1) g_wbar[col] = (part[threadIdx.x & 127] + s) * (1.0f / UU);
    if (blockIdx.x == 0 && threadIdx.x == 0) {
        float b = 0.f;
        for (int i = 0; i < UU; i++) b += bias[i];
        g_bmean = b * (1.0f / UU);
    }
}

// B[j,k] = tf32(Adj[j,k] * wbar[k])
__global__ void conv_B_kernel(const float* __restrict__ Adj) {
    size_t base = ((size_t)blockIdx.x * blockDim.x + threadIdx.x) * 4;
    float4 a = *reinterpret_cast<const float4*>(Adj + base);
    int k0 = (int)(base & (NDIM - 1));
    float4 wb = *reinterpret_cast<const float4*>(g_wbar + k0);
    uint4 o;
    o.x = f2tf32(a.x * wb.x);
    o.y = f2tf32(a.y * wb.y);
    o.z = f2tf32(a.z * wb.z);
    o.w = f2tf32(a.w * wb.w);
    *reinterpret_cast<uint4*>(reinterpret_cast<uint32_t*>(g_B) + base) = o;
}

// ----------------------------------------------------------------------------
// GEMM: out[m, j] = sum_k tf32(x[m,k]) * B[j,k] + bmean
// CTA tile 128x128, 128 threads = 4 warps in 2x2 grid, warp tile 64x64.
// KC=32 fp32 (128B rows), 3-stage cp.async pipeline, 2 CTAs/SM.
// A raw fp32 from x; cvt.rna.tf32 applied in registers post-ldmatrix.
// ----------------------------------------------------------------------------
static constexpr int TM = 128;
static constexpr int TN = 128;
static constexpr int KC = 32;                  // floats per k-chunk
static constexpr int NKC = NDIM / KC;          // 64
static constexpr int STAGES = 3;

static constexpr int A_STAGE = TM * 128;       // 16384 B (128B per row)
static constexpr int B_STAGE = TN * 128;       // 16384 B
static constexpr int STAGE_BYTES = A_STAGE + B_STAGE;      // 32768
static constexpr int SMEM_TOTAL = STAGES * STAGE_BYTES;    // 98304

// swizzled offset within a tile: row (0..127) x 16B-chunk c (0..7)
__device__ __forceinline__ uint32_t swz(int row, int c) {
    return (uint32_t)(row * 128 + ((c ^ (row & 7)) << 4));
}

__global__ __launch_bounds__(128, 2) void gemm_kernel(const float* __restrict__ x,
                                                      float* __restrict__ out) {
    extern __shared__ char smem[];
    uint32_t sb = smem_to_u32(smem);

    const int tid = threadIdx.x;
    const int wid = tid >> 5, lid = tid & 31;
    const int wm = wid >> 1;          // 0..1  (64 rows each)
    const int wn = wid & 1;           // 0..1  (64 cols each)
    const int m0 = blockIdx.y * TM;
    const int n0 = blockIdx.x * TN;

    const char* gA = reinterpret_cast<const char*>(x   + (size_t)m0 * NDIM);
    const char* gB = reinterpret_cast<const char*>(g_B + (size_t)n0 * NDIM);

    // 2048 granules (1024 A + 1024 B), 16 per thread
    auto load_stage = [&](int kc, int stage) {
        uint32_t abase = sb + stage * STAGE_BYTES;
        uint32_t bbase = abase + A_STAGE;
        size_t koff = (size_t)kc * KC * 4;
        #pragma unroll
        for (int j = 0; j < 16; j++) {
            int gi = tid + j * 128;
            int r = (gi >> 3) & 127, c = gi & 7;
            if (gi < 1024) {
                cp16(abase + swz(r, c), gA + (size_t)r * (NDIM * 4) + koff + c * 16);
            } else {
                cp16(bbase + swz(r, c), gB + (size_t)r * (NDIM * 4) + koff + c * 16);
            }
        }
    };

    // ldmatrix per-thread roles
    const int aRowOff = (lid & 15);
    const int aCsel = lid >> 4;
    const int bRowOff = (lid & 7) + ((lid >> 4) << 3);
    const int bCsel = (lid >> 3) & 1;

    float acc[4][8][4];
    #pragma unroll
    for (int i = 0; i < 4; i++)
        #pragma unroll
        for (int j = 0; j < 8; j++)
            #pragma unroll
            for (int q = 0; q < 4; q++) acc[i][j][q] = 0.f;

    #pragma unroll
    for (int s = 0; s < STAGES - 1; s++) { load_stage(s, s); cp_commit(); }

    int stage = 0;
    for (int i = 0; i < NKC; i++) {
        cp_wait<STAGES - 2>();
        __syncthreads();

        uint32_t abase = sb + stage * STAGE_BYTES;
        uint32_t bbase = abase + A_STAGE;

        #pragma unroll
        for (int ks = 0; ks < KC / 8; ks++) {
            uint32_t aR[4][4], bR[4][4];
            #pragma unroll
            for (int mb = 0; mb < 4; mb++) {
                int row = wm * 64 + mb * 16 + aRowOff;
                ldm_x4(aR[mb], abase + swz(row, ks * 2 + aCsel));
                #pragma unroll
                for (int q = 0; q < 4; q++)
                    aR[mb][q] = f2tf32(__uint_as_float(aR[mb][q]));
            }
            #pragma unroll
            for (int bp = 0; bp < 4; bp++) {
                int row = wn * 64 + bp * 16 + bRowOff;
                ldm_x4(bR[bp], bbase + swz(row, ks * 2 + bCsel));
            }

            if (ks == 0) {
                int nxt = i + STAGES - 1;
                if (nxt < NKC) {
                    int nstage = stage + (STAGES - 1);
                    if (nstage >= STAGES) nstage -= STAGES;
                    load_stage(nxt, nstage);
                }
                cp_commit();
            }

            #pragma unroll
            for (int mb = 0; mb < 4; mb++) {
                #pragma unroll
                for (int nb = 0; nb < 8; nb++) {
                    mma_tf32(acc[mb][nb], aR[mb], &bR[nb >> 1][(nb & 1) * 2]);
                }
            }
        }

        stage++;
        if (stage == STAGES) stage = 0;
    }

    // Epilogue: each warp writes its 64x64 block
    float bm = g_bmean;
    #pragma unroll
    for (int mb = 0; mb < 4; mb++) {
        int row = m0 + wm * 64 + mb * 16 + (lid >> 2);
        #pragma unroll
        for (int nb = 0; nb < 8; nb++) {
            int col = n0 + wn * 64 + nb * 8 + (lid & 3) * 2;
            float2 v0, v1;
            v0.x = acc[mb][nb][0] + bm;
            v0.y = acc[mb][nb][1] + bm;
            v1.x = acc[mb][nb][2] + bm;
            v1.y = acc[mb][nb][3] + bm;
            *reinterpret_cast<float2*>(out + (size_t)row * NDIM + col) = v0;
            *reinterpret_cast<float2*>(out + (size_t)(row + 8) * NDIM + col) = v1;
        }
    }
}

// ----------------------------------------------------------------------------
// Launch
// ----------------------------------------------------------------------------
extern "C" void kernel_launch(void* const* d_in, const int* in_sizes, int n_in,
                              void* d_out, int out_size) {
    const float* x    = (const float*)d_in[0];   // [16, 512, 2048]
    const float* Adj  = (const float*)d_in[1];   // [2048, 2048]
    const float* W    = (const float*)d_in[2];   // [64, 2048]
    const float* bias = (const float*)d_in[3];   // [64]
    float* out = (float*)d_out;                  // [16, 512, 2048]

    prep_wbar_kernel<<<16, 256>>>(W, bias);
    conv_B_kernel<<<(NDIM * NDIM / 4) / 256, 256>>>(Adj);

    cudaFuncSetAttribute(gemm_kernel, cudaFuncAttributeMaxDynamicSharedMemorySize, SMEM_TOTAL);
    gemm_kernel<<<dim3(NDIM / TN, MTOT / TM), 128, SMEM_TOTAL>>>(x, out);
}